// round 4
// baseline (speedup 1.0000x reference)
#include <cuda_runtime.h>
#include <math.h>

// ---------------- problem constants ----------------
#define HEADS  8
#define HD     128          // head dim = 3072 / (3*8)
#define NSEQ   1024
#define DIM    512
#define INNER  3072
#define BATCH  8            // bt*b_sz = 2*4
#define BH     (BATCH*HEADS)    // 64
#define NTOK   (BATCH*NSEQ)     // 8192
#define SCALE  0.125f       // (dim // HEADS)^-0.5 = 64^-0.5

// ---------------- scratch (device globals) ----------------
__device__ float g_Q[BH * NSEQ * HD];    // [bh][n][d]
__device__ float g_K[BH * NSEQ * HD];    // [bh][n][d]
__device__ float g_V[BH * NSEQ * HD];    // [bh][n][d]
__device__ float g_O[NTOK * HEADS * HD]; // [token][h*128+dd]

// ---------------- tf32 helpers ----------------
__device__ __forceinline__ unsigned f2tf(float x) {
    unsigned r;
    asm("cvt.rna.tf32.f32 %0, %1;" : "=r"(r) : "f"(x));
    return r;
}

__device__ __forceinline__ void mma8(float* c, const unsigned* a, unsigned b0, unsigned b1) {
    asm volatile(
        "mma.sync.aligned.m16n8k8.row.col.f32.tf32.tf32.f32 "
        "{%0,%1,%2,%3}, {%4,%5,%6,%7}, {%8,%9}, {%0,%1,%2,%3};\n"
        : "+f"(c[0]), "+f"(c[1]), "+f"(c[2]), "+f"(c[3])
        : "r"(a[0]), "r"(a[1]), "r"(a[2]), "r"(a[3]), "r"(b0), "r"(b1));
}

// =====================================================================
// tf32 MMA GEMM: C(MxN) = A(MxK) @ B(KxN) + bias
// 128x128x32 CTA tile, 8 warps, warp tile 64x32 (2x4 warp grid).
// EPI==0: A=x, epilogue scatters into g_Q/g_K/g_V  (N=3072)
// EPI==1: A=g_O, epilogue writes C=d_out           (N=512)
// =====================================================================
#define AP 36     // As pitch (floats): frag addr 4g+tg -> conflict-free
#define BP 136    // Bs pitch: frag addr 8tg+g -> conflict-free

template<int EPI>
__global__ void __launch_bounds__(256)
mma_gemm(const float* __restrict__ A, const float* __restrict__ B,
         const float* __restrict__ bias, float* __restrict__ C,
         int M, int N, int K)
{
    __shared__ unsigned As[128 * AP];
    __shared__ unsigned Bs[32 * BP];

    const int tid  = threadIdx.x;
    const int warp = tid >> 5;
    const int lane = tid & 31;
    const int g    = lane >> 2;
    const int tg   = lane & 3;
    const int wr   = warp >> 2;   // 0..1
    const int wc   = warp & 3;    // 0..3

    const int rowBase = blockIdx.y * 128;
    const int colBase = blockIdx.x * 128;

    const float* Asrc = (EPI == 1) ? g_O : A;

    float c[4][4][4] = {};

    for (int k0 = 0; k0 < K; k0 += 32) {
        // stage A tile (128x32) as tf32
        #pragma unroll
        for (int i = 0; i < 4; i++) {
            int f  = tid + i * 256;           // float4 index, 1024 total
            int m  = f >> 3;
            int kc = (f & 7) << 2;
            float4 v = *(const float4*)(Asrc + (size_t)(rowBase + m) * K + k0 + kc);
            As[m * AP + kc + 0] = f2tf(v.x);
            As[m * AP + kc + 1] = f2tf(v.y);
            As[m * AP + kc + 2] = f2tf(v.z);
            As[m * AP + kc + 3] = f2tf(v.w);
        }
        // stage B tile (32x128) as tf32
        #pragma unroll
        for (int i = 0; i < 4; i++) {
            int f  = tid + i * 256;
            int kr = f >> 5;
            int nc = (f & 31) << 2;
            float4 v = *(const float4*)(B + (size_t)(k0 + kr) * N + colBase + nc);
            Bs[kr * BP + nc + 0] = f2tf(v.x);
            Bs[kr * BP + nc + 1] = f2tf(v.y);
            Bs[kr * BP + nc + 2] = f2tf(v.z);
            Bs[kr * BP + nc + 3] = f2tf(v.w);
        }
        __syncthreads();

        #pragma unroll
        for (int ks = 0; ks < 4; ks++) {
            const int kb = ks * 8;
            unsigned a[4][4], b[4][2];
            #pragma unroll
            for (int mt = 0; mt < 4; mt++) {
                const int rb = wr * 64 + mt * 16;
                a[mt][0] = As[(rb + g)     * AP + kb + tg];
                a[mt][1] = As[(rb + g + 8) * AP + kb + tg];
                a[mt][2] = As[(rb + g)     * AP + kb + tg + 4];
                a[mt][3] = As[(rb + g + 8) * AP + kb + tg + 4];
            }
            #pragma unroll
            for (int nt = 0; nt < 4; nt++) {
                const int cb = wc * 32 + nt * 8;
                b[nt][0] = Bs[(kb + tg)     * BP + cb + g];
                b[nt][1] = Bs[(kb + tg + 4) * BP + cb + g];
            }
            #pragma unroll
            for (int mt = 0; mt < 4; mt++)
                #pragma unroll
                for (int nt = 0; nt < 4; nt++)
                    mma8(c[mt][nt], a[mt], b[nt][0], b[nt][1]);
        }
        __syncthreads();
    }

    // ---------------- epilogue ----------------
    #pragma unroll
    for (int mt = 0; mt < 4; mt++) {
        const int r0 = rowBase + wr * 64 + mt * 16 + g;
        const int r1 = r0 + 8;
        #pragma unroll
        for (int nt = 0; nt < 4; nt++) {
            const int col0 = colBase + wc * 32 + nt * 8 + 2 * tg;
            const float b0 = bias[col0], b1 = bias[col0 + 1];
            float2 v0 = { c[mt][nt][0] + b0, c[mt][nt][1] + b1 };  // row r0
            float2 v1 = { c[mt][nt][2] + b0, c[mt][nt][3] + b1 };  // row r1
            if (EPI == 0) {
                const int part = col0 >> 10;
                const int h    = (col0 >> 7) & 7;
                const int dd   = col0 & 127;
                float* dst = (part == 0) ? g_Q : (part == 1) ? g_K : g_V;
                {
                    const int bh = (r0 >> 10) * HEADS + h;
                    const int ni = r0 & 1023;
                    *(float2*)(dst + ((size_t)bh * NSEQ + ni) * HD + dd) = v0;
                }
                {
                    const int bh = (r1 >> 10) * HEADS + h;
                    const int ni = r1 & 1023;
                    *(float2*)(dst + ((size_t)bh * NSEQ + ni) * HD + dd) = v1;
                }
            } else {
                *(float2*)(C + (size_t)r0 * N + col0) = v0;
                *(float2*)(C + (size_t)r1 * N + col0) = v1;
            }
        }
    }
}

// =====================================================================
// tf32 MMA flash attention.
// grid = (8 q-tiles, 64 bh), block = 256 (8 warps).
// CTA: 128 q rows; warp w owns rows [16w,16w+16). kv tiles of 64, 16 iters.
// S: warp computes 16x64 via 8 n-tiles m16n8k8 over d=128 (16 k-steps).
// PV: warp computes 16x128 via 16 n-tiles over kv=64 (8 k-steps).
// =====================================================================
#define QP 132   // sQ pitch: frag addr 4g+tg conflict-free
#define KP 132   // sK pitch: frag addr 4g+tg conflict-free
#define VP 136   // sV pitch: frag addr 8tg+g conflict-free
#define PP 68    // sP pitch: frag addr 4g+tg conflict-free

#define ATT_SMEM_UINTS (128*QP + 64*KP + 64*VP + 128*PP)
#define ATT_SMEM_BYTES (ATT_SMEM_UINTS * 4)

__global__ void __launch_bounds__(256)
attn_mma()
{
    extern __shared__ unsigned sm[];
    unsigned* sQ = sm;                 // [128][QP]
    unsigned* sK = sQ + 128 * QP;      // [64][KP]
    unsigned* sV = sK + 64 * KP;       // [64][VP]
    unsigned* sP = sV + 64 * VP;       // [128][PP]

    const int bh  = blockIdx.y;
    const int q0  = blockIdx.x * 128;
    const int tid = threadIdx.x;
    const int warp = tid >> 5;
    const int lane = tid & 31;
    const int g    = lane >> 2;
    const int tg   = lane & 3;
    const int wrow = warp * 16;

    const float* Qg = g_Q + ((size_t)bh * NSEQ + q0) * HD;
    const float* Kg = g_K + (size_t)bh * NSEQ * HD;
    const float* Vg = g_V + (size_t)bh * NSEQ * HD;

    // load Q tile (128 x 128) -> tf32
    #pragma unroll
    for (int i = 0; i < 16; i++) {
        int f  = tid + i * 256;       // of 4096 float4
        int r  = f >> 5;
        int c4 = (f & 31) << 2;
        float4 v = *(const float4*)(Qg + (size_t)r * HD + c4);
        sQ[r * QP + c4 + 0] = f2tf(v.x);
        sQ[r * QP + c4 + 1] = f2tf(v.y);
        sQ[r * QP + c4 + 2] = f2tf(v.z);
        sQ[r * QP + c4 + 3] = f2tf(v.w);
    }

    float o[16][4] = {};
    float rm0 = -1e30f, rm1 = -1e30f, rl0 = 0.f, rl1 = 0.f;

    for (int t = 0; t < 16; t++) {
        const int n0 = t * 64;
        __syncthreads();   // previous iter done with sK/sV

        #pragma unroll
        for (int i = 0; i < 8; i++) {
            int f  = tid + i * 256;   // of 2048 float4
            int r  = f >> 5;
            int c4 = (f & 31) << 2;
            float4 kv = *(const float4*)(Kg + (size_t)(n0 + r) * HD + c4);
            sK[r * KP + c4 + 0] = f2tf(kv.x);
            sK[r * KP + c4 + 1] = f2tf(kv.y);
            sK[r * KP + c4 + 2] = f2tf(kv.z);
            sK[r * KP + c4 + 3] = f2tf(kv.w);
            float4 vv = *(const float4*)(Vg + (size_t)(n0 + r) * HD + c4);
            sV[r * VP + c4 + 0] = f2tf(vv.x);
            sV[r * VP + c4 + 1] = f2tf(vv.y);
            sV[r * VP + c4 + 2] = f2tf(vv.z);
            sV[r * VP + c4 + 3] = f2tf(vv.w);
        }
        __syncthreads();

        // ---- S = Q @ K^T : cs[8][4] ----
        float cs[8][4] = {};
        #pragma unroll 4
        for (int ks = 0; ks < 16; ks++) {
            const int kb = ks * 8;
            unsigned a[4];
            a[0] = sQ[(wrow + g)     * QP + kb + tg];
            a[1] = sQ[(wrow + g + 8) * QP + kb + tg];
            a[2] = sQ[(wrow + g)     * QP + kb + tg + 4];
            a[3] = sQ[(wrow + g + 8) * QP + kb + tg + 4];
            #pragma unroll
            for (int nt = 0; nt < 8; nt++) {
                unsigned b0 = sK[(nt * 8 + g) * KP + kb + tg];
                unsigned b1 = sK[(nt * 8 + g) * KP + kb + tg + 4];
                mma8(cs[nt], a, b0, b1);
            }
        }

        // ---- online softmax on fragments ----
        #pragma unroll
        for (int nt = 0; nt < 8; nt++) {
            cs[nt][0] *= SCALE; cs[nt][1] *= SCALE;
            cs[nt][2] *= SCALE; cs[nt][3] *= SCALE;
        }
        float mx0 = -1e30f, mx1 = -1e30f;
        #pragma unroll
        for (int nt = 0; nt < 8; nt++) {
            mx0 = fmaxf(mx0, fmaxf(cs[nt][0], cs[nt][1]));
            mx1 = fmaxf(mx1, fmaxf(cs[nt][2], cs[nt][3]));
        }
        mx0 = fmaxf(mx0, __shfl_xor_sync(0xffffffffu, mx0, 1));
        mx0 = fmaxf(mx0, __shfl_xor_sync(0xffffffffu, mx0, 2));
        mx1 = fmaxf(mx1, __shfl_xor_sync(0xffffffffu, mx1, 1));
        mx1 = fmaxf(mx1, __shfl_xor_sync(0xffffffffu, mx1, 2));

        const float mn0 = fmaxf(rm0, mx0);
        const float mn1 = fmaxf(rm1, mx1);
        const float alpha0 = __expf(rm0 - mn0);
        const float alpha1 = __expf(rm1 - mn1);
        rm0 = mn0; rm1 = mn1;

        float ls0 = 0.f, ls1 = 0.f;
        #pragma unroll
        for (int nt = 0; nt < 8; nt++) {
            const float p0 = __expf(cs[nt][0] - mn0);
            const float p1 = __expf(cs[nt][1] - mn0);
            const float p2 = __expf(cs[nt][2] - mn1);
            const float p3 = __expf(cs[nt][3] - mn1);
            ls0 += p0 + p1;
            ls1 += p2 + p3;
            const int col = nt * 8 + 2 * tg;
            sP[(wrow + g)     * PP + col]     = f2tf(p0);
            sP[(wrow + g)     * PP + col + 1] = f2tf(p1);
            sP[(wrow + g + 8) * PP + col]     = f2tf(p2);
            sP[(wrow + g + 8) * PP + col + 1] = f2tf(p3);
        }
        ls0 += __shfl_xor_sync(0xffffffffu, ls0, 1);
        ls0 += __shfl_xor_sync(0xffffffffu, ls0, 2);
        ls1 += __shfl_xor_sync(0xffffffffu, ls1, 1);
        ls1 += __shfl_xor_sync(0xffffffffu, ls1, 2);
        rl0 = rl0 * alpha0 + ls0;
        rl1 = rl1 * alpha1 + ls1;

        #pragma unroll
        for (int nt2 = 0; nt2 < 16; nt2++) {
            o[nt2][0] *= alpha0; o[nt2][1] *= alpha0;
            o[nt2][2] *= alpha1; o[nt2][3] *= alpha1;
        }
        __syncwarp();   // sP rows written by this warp, read by this warp

        // ---- O += P @ V ----
        #pragma unroll
        for (int ks = 0; ks < 8; ks++) {
            const int kb = ks * 8;
            unsigned a[4];
            a[0] = sP[(wrow + g)     * PP + kb + tg];
            a[1] = sP[(wrow + g + 8) * PP + kb + tg];
            a[2] = sP[(wrow + g)     * PP + kb + tg + 4];
            a[3] = sP[(wrow + g + 8) * PP + kb + tg + 4];
            #pragma unroll
            for (int nt2 = 0; nt2 < 16; nt2++) {
                unsigned b0 = sV[(kb + tg)     * VP + nt2 * 8 + g];
                unsigned b1 = sV[(kb + tg + 4) * VP + nt2 * 8 + g];
                mma8(o[nt2], a, b0, b1);
            }
        }
        __syncwarp();   // done reading sP before next-iter rewrite
    }

    // ---- finalize ----
    const float inv0 = 1.0f / rl0;
    const float inv1 = 1.0f / rl1;
    const int bidx = bh >> 3;
    const int h    = bh & 7;
    const int ni0  = q0 + wrow + g;
    const int ni1  = ni0 + 8;
    float* O0 = g_O + ((size_t)(bidx * NSEQ + ni0)) * (HEADS * HD) + h * HD;
    float* O1 = g_O + ((size_t)(bidx * NSEQ + ni1)) * (HEADS * HD) + h * HD;
    #pragma unroll
    for (int nt2 = 0; nt2 < 16; nt2++) {
        const int col = nt2 * 8 + 2 * tg;
        float2 v0 = { o[nt2][0] * inv0, o[nt2][1] * inv0 };
        float2 v1 = { o[nt2][2] * inv1, o[nt2][3] * inv1 };
        *(float2*)(O0 + col) = v0;
        *(float2*)(O1 + col) = v1;
    }
}

// =====================================================================
// launch
// =====================================================================
extern "C" void kernel_launch(void* const* d_in, const int* in_sizes, int n_in,
                              void* d_out, int out_size)
{
    const float *x = nullptr, *Wqkv = nullptr, *bqkv = nullptr,
                *Wout = nullptr, *bout = nullptr;
    for (int i = 0; i < n_in; i++) {
        switch (in_sizes[i]) {
            case NTOK * DIM:  x    = (const float*)d_in[i]; break;
            case DIM * INNER: Wqkv = (const float*)d_in[i]; break;
            case INNER:       bqkv = (const float*)d_in[i]; break;
            case 1024 * DIM:  Wout = (const float*)d_in[i]; break;
            case DIM:         bout = (const float*)d_in[i]; break;
        }
    }
    float* out = (float*)d_out;

    (void)cudaFuncSetAttribute(attn_mma,
                               cudaFuncAttributeMaxDynamicSharedMemorySize,
                               ATT_SMEM_BYTES);

    // 1) QKV projection + scatter (M=8192, N=3072, K=512)
    mma_gemm<0><<<dim3(INNER / 128, NTOK / 128), 256>>>(
        x, Wqkv, bqkv, nullptr, NTOK, INNER, DIM);

    // 2) attention (tf32 mma flash)
    attn_mma<<<dim3(NSEQ / 128, BH), 256, ATT_SMEM_BYTES>>>();

    // 3) output projection (M=8192, N=512, K=1024)
    mma_gemm<1><<<dim3(DIM / 128, NTOK / 128), 256>>>(
        nullptr, Wout, bout, out, NTOK, DIM, HEADS * HD);
}